// round 9
// baseline (speedup 1.0000x reference)
#include <cuda_runtime.h>
#include <cuda_bf16.h>
#include <cstdint>

// ---------------- scratch (no runtime allocation) ----------------
__device__ __align__(16) unsigned int g_tgt2[8 * 4096 * 16];     // 2 MiB: 2-bit classes [b][l][ky]
__device__ __align__(16) signed char  g_uconv8[32 * 256 * 256];  // 2 MiB: counts [b*4+c][m][k], 0..16
__device__ double g_acc;
__device__ int    g_is32;

// ---------------- helpers ----------------
__device__ __forceinline__ uint32_t smem_u32(const void* p) {
    uint32_t a;
    asm("{ .reg .u64 t; cvta.to.shared.u64 t, %1; cvt.u32.u64 %0, t; }" : "=r"(a) : "l"(p));
    return a;
}

#define ST4(addr, a, b, c, d) \
    asm volatile("st.shared.v4.b32 [%0], {%1,%2,%3,%4};" :: "r"(addr), "r"(a), "r"(b), "r"(c), "r"(d) : "memory")

__device__ __forceinline__ void ldsm_x4(uint32_t& r0, uint32_t& r1, uint32_t& r2, uint32_t& r3, uint32_t addr) {
    asm volatile("ldmatrix.sync.aligned.m8n8.x4.shared.b16 {%0,%1,%2,%3}, [%4];"
                 : "=r"(r0), "=r"(r1), "=r"(r2), "=r"(r3) : "r"(addr));
}
__device__ __forceinline__ void ldsm_x2(uint32_t& r0, uint32_t& r1, uint32_t addr) {
    asm volatile("ldmatrix.sync.aligned.m8n8.x2.shared.b16 {%0,%1}, [%2];"
                 : "=r"(r0), "=r"(r1) : "r"(addr));
}
__device__ __forceinline__ void imma_s8(int& c0, int& c1, int& c2, int& c3,
                                        uint32_t a0, uint32_t a1, uint32_t a2, uint32_t a3,
                                        uint32_t b0, uint32_t b1) {
    asm volatile("mma.sync.aligned.m16n8k32.row.col.s32.s8.s8.s32 "
                 "{%0,%1,%2,%3}, {%4,%5,%6,%7}, {%8,%9}, {%0,%1,%2,%3};"
                 : "+r"(c0), "+r"(c1), "+r"(c2), "+r"(c3)
                 : "r"(a0), "r"(a1), "r"(a2), "r"(a3), "r"(b0), "r"(b1));
}

// ---------------- tiny kernels ----------------
__global__ void zero_kernel() { g_acc = 0.0; g_is32 = 0; }

__global__ void detect_kernel(const unsigned int* __restrict__ t) {
    unsigned int any = 0;
    for (int i = threadIdx.x; i < 8192; i += 256) any |= t[2 * i + 1];
    if (any) g_is32 = 1;   // int32 data: odd words carry real values (nonzero w.h.p.)
}

__global__ void finalize_kernel(float* __restrict__ out) {
    out[0] = (float)(g_acc * (1.0 / 33554432.0));
}

// ---------------- prep: target -> packed 2-bit patch codes + pooled s8 counts ----------------
// grid 128 = 8 b * 16 slabs of 64 rows; 512 threads
__global__ void __launch_bounds__(512) prep_kernel(const void* __restrict__ traw) {
    __shared__ unsigned s_cls[4096];   // [y_local 0..63][x/16], 16 px per word, 2 bits each
    int b = blockIdx.x >> 4, slab = blockIdx.x & 15;

    if (g_is32) {
        const uint4* tb = (const uint4*)((const int*)traw + (((size_t)b) << 20) + (((size_t)slab) << 16));
        for (int w = threadIdx.x; w < 4096; w += 512) {
            int y = w >> 6, xw = w & 63;
            const uint4* p = tb + y * 256 + xw * 4;
            unsigned packed = 0;
#pragma unroll
            for (int i = 0; i < 4; i++) {
                uint4 v = p[i];
                packed |= (v.x & 3u) << (8 * i);
                packed |= (v.y & 3u) << (8 * i + 2);
                packed |= (v.z & 3u) << (8 * i + 4);
                packed |= (v.w & 3u) << (8 * i + 6);
            }
            s_cls[w] = packed;
        }
    } else {
        const longlong2* tb = (const longlong2*)((const long long*)traw + (((size_t)b) << 20) + (((size_t)slab) << 16));
        for (int w = threadIdx.x; w < 4096; w += 512) {
            int y = w >> 6, xw = w & 63;
            const longlong2* p = tb + y * 512 + xw * 8;
            unsigned packed = 0;
#pragma unroll
            for (int i = 0; i < 8; i++) {
                longlong2 v = p[i];
                packed |= ((unsigned)v.x & 3u) << (4 * i);
                packed |= ((unsigned)v.y & 3u) << (4 * i + 2);
            }
            s_cls[w] = packed;
        }
    }
    __syncthreads();

    // --- tgt2: per patch l, 16 words (one per ky), each word = 16 kx classes ---
    unsigned* outb = g_tgt2 + ((size_t)(b * 4096 + slab * 256)) * 16;
    for (int o = threadIdx.x; o < 4096; o += 512) {
        int ky = o >> 8, l_loc = o & 255;
        int Yl = l_loc >> 6, Xl = l_loc & 63;
        outb[l_loc * 16 + ky] = s_cls[(Yl * 16 + ky) * 64 + Xl];
    }

    // --- u_conv counts: 4x4 pooled one-hot * 16, written transposed as [bc][m][k] s8 ---
    for (int o = threadIdx.x; o < 4096; o += 512) {
        int yb = o >> 8, xb = o & 255;          // pooled coords (local row, col)
        unsigned w32 = 0;
#pragma unroll
        for (int rr = 0; rr < 4; rr++) {
            unsigned wd = s_cls[(yb * 4 + rr) * 64 + (xb >> 2)];
            w32 |= ((wd >> (8 * (xb & 3))) & 0xFFu) << (8 * rr);   // 16 codes of this 4x4 block
        }
        int y = slab * 16 + yb;                 // global pooled row 0..255
        int m = ((y >> 4) * 16) + (xb >> 4);
        int k = ((y & 15) * 16) + (xb & 15);
#pragma unroll
        for (unsigned c = 0; c < 4; c++) {
            unsigned t = w32 ^ (0x55555555u * c);
            unsigned u = (~t) & ((~t) >> 1) & 0x55555555u;
            g_uconv8[(((size_t)b * 4 + c) * 256 + m) * 256 + k] = (signed char)__popc(u);
        }
    }
}

// ---------------- GEMM (mma.sync s8 k32) + fused epilogue ----------------
// smem: A 128x256 s8 (32 KB), B 256x256 s8 (64 KB); rows 256 B, 16B-chunk XOR swizzle.
#define SM_A      0
#define SM_B      32768
#define SM_TOTAL  (32768 + 65536)

__global__ void __launch_bounds__(256, 2) gemm_kernel(const float* __restrict__ att) {
    extern __shared__ char smem[];
    __shared__ float s_ws[8];
    uint32_t sbase = smem_u32(smem);
    int tid = threadIdx.x, wid = tid >> 5, ln = tid & 31;
    int bc = blockIdx.x >> 5;          // b*4+c
    int lt = blockIdx.x & 31;          // 128-row l tile

    // kick DRAM first: prefetch this CTA's 128 KB attentions tile into L2
    const float* atile = att + ((size_t)bc * 4096 + (size_t)lt * 128) * 256;
    for (int i = tid; i < 1024; i += 256)
        asm volatile("prefetch.global.L2 [%0];" :: "l"(atile + i * 32));

    // ---- A fill: expand 2-bit class codes -> s8 {0,1}, rows 256 B ----
    {
        int b = bc >> 2;
        unsigned c = (unsigned)(bc & 3);
        int l_loc = tid >> 1, half = tid & 1;
        const unsigned* wp = g_tgt2 + ((size_t)(b * 4096 + lt * 128 + l_loc)) * 16 + half * 8;
        uint4 wA = ((const uint4*)wp)[0];
        uint4 wB = ((const uint4*)wp)[1];
        unsigned ws8[8] = {wA.x, wA.y, wA.z, wA.w, wB.x, wB.y, wB.z, wB.w};
        uint32_t rowoff = sbase + SM_A + (uint32_t)(l_loc * 256);
        uint32_t sw = (uint32_t)((l_loc & 7) << 4);
#pragma unroll
        for (int q = 0; q < 8; q++) {
            unsigned w = ws8[q];
            unsigned t = w ^ (0x55555555u * c);
            unsigned u = (~t) & ((~t) >> 1) & 0x55555555u;
            uint32_t o[4];
#pragma unroll
            for (int i = 0; i < 4; i++) {
                uint32_t x = (u >> (8 * i)) & 0xFFu;
                o[i] = (x & 1u) | ((x & 4u) << 6) | ((x & 0x10u) << 12) | ((x & 0x40u) << 18);
            }
            uint32_t kb = (uint32_t)((half * 8 + q) * 16);
            ST4(rowoff + (kb ^ sw), o[0], o[1], o[2], o[3]);
        }
    }

    // ---- B fill: counts [m][k] s8 (64 KB) from L2-resident g_uconv8 ----
    {
        const uint4* src = (const uint4*)(g_uconv8 + (size_t)bc * 65536);
        for (int idx = tid; idx < 4096; idx += 256) {
            int m = idx >> 4, u = idx & 15;
            uint4 v = src[idx];
            uint32_t addr = sbase + SM_B + (uint32_t)(m * 256) +
                            (((uint32_t)(u * 16)) ^ (uint32_t)((m & 7) << 4));
            ST4(addr, v.x, v.y, v.z, v.w);
        }
    }
    __syncthreads();

    // ---- per-warp tile: 32 l-rows x 128 m-cols, m in 2 chunks of 64 ----
    int l_base = (wid & 3) * 32;
    int m_half = (wid >> 2) * 128;

    uint32_t aRow0 = sbase + SM_A + (uint32_t)((l_base + (ln & 15)) * 256);
    uint32_t aRow1 = aRow0 + 16 * 256;
    uint32_t aswz = (uint32_t)((ln & 7) << 4);
    uint32_t akofs = (uint32_t)((ln >> 4) * 16);     // k16-byte half for quads 2/3
    uint32_t bkofs = (uint32_t)(((ln >> 3) & 1) * 16);

    float wsum = 0.f;
    const float s4096 = 1.f / 4096.f;

#pragma unroll
    for (int mc = 0; mc < 2; mc++) {
        int mb = m_half + mc * 64;
        int acc[64];
#pragma unroll
        for (int i = 0; i < 64; i++) acc[i] = 0;

        uint32_t bBase = sbase + SM_B + (uint32_t)((mb + (ln & 7)) * 256);

#pragma unroll
        for (int s = 0; s < 8; s++) {
            uint32_t ka = (uint32_t)(s * 32) + akofs;
            uint32_t a0, a1, a2, a3, a4, a5, a6, a7;
            ldsm_x4(a0, a1, a2, a3, aRow0 + (ka ^ aswz));
            ldsm_x4(a4, a5, a6, a7, aRow1 + (ka ^ aswz));
            uint32_t kb = (uint32_t)(s * 32) + bkofs;
            uint32_t bf[16];
#pragma unroll
            for (int j = 0; j < 8; j++)
                ldsm_x2(bf[2 * j], bf[2 * j + 1], bBase + (uint32_t)(j * 2048) + (kb ^ aswz));
#pragma unroll
            for (int j = 0; j < 8; j++) {
                imma_s8(acc[j * 4 + 0], acc[j * 4 + 1], acc[j * 4 + 2], acc[j * 4 + 3],
                        a0, a1, a2, a3, bf[2 * j], bf[2 * j + 1]);
                imma_s8(acc[32 + j * 4 + 0], acc[32 + j * 4 + 1], acc[32 + j * 4 + 2], acc[32 + j * 4 + 3],
                        a4, a5, a6, a7, bf[2 * j], bf[2 * j + 1]);
            }
        }

        // ---- fused epilogue for this m-chunk: (att - acc/4096)^2 ----
#pragma unroll
        for (int i = 0; i < 2; i++) {
            int R = l_base + i * 16 + (ln >> 2);
#pragma unroll
            for (int j = 0; j < 8; j++) {
                int C = mb + j * 8 + (ln & 3) * 2;
                float2 t0 = __ldg((const float2*)(atile + (size_t)R * 256 + C));
                float2 t1 = __ldg((const float2*)(atile + (size_t)(R + 8) * 256 + C));
                int* a = &acc[i * 32 + j * 4];
                float d0 = t0.x - (float)a[0] * s4096;
                float d1 = t0.y - (float)a[1] * s4096;
                float d2 = t1.x - (float)a[2] * s4096;
                float d3 = t1.y - (float)a[3] * s4096;
                wsum += d0 * d0 + d1 * d1 + d2 * d2 + d3 * d3;
            }
        }
    }

    // ---- reduce: warp -> CTA -> one double atomic per CTA ----
#pragma unroll
    for (int off = 16; off; off >>= 1) wsum += __shfl_xor_sync(0xFFFFFFFFu, wsum, off);
    if (ln == 0) s_ws[wid] = wsum;
    __syncthreads();
    if (tid == 0) {
        float t = 0.f;
#pragma unroll
        for (int i = 0; i < 8; i++) t += s_ws[i];
        atomicAdd(&g_acc, (double)t);
    }
}

// ---------------- launch ----------------
extern "C" void kernel_launch(void* const* d_in, const int* in_sizes, int n_in,
                              void* d_out, int out_size) {
    const void*  target = d_in[1];               // int64 or int32 (runtime-detected)
    const float* att    = (const float*)d_in[2]; // (8,4,4096,256)
    (void)in_sizes; (void)n_in; (void)out_size;

    cudaFuncSetAttribute(gemm_kernel, cudaFuncAttributeMaxDynamicSharedMemorySize, SM_TOTAL);

    zero_kernel<<<1, 1>>>();
    detect_kernel<<<1, 256>>>((const unsigned int*)target);
    prep_kernel<<<128, 512>>>(target);
    gemm_kernel<<<1024, 256, SM_TOTAL>>>(att);
    finalize_kernel<<<1, 1>>>((float*)d_out);
}

// round 12
// speedup vs baseline: 1.6028x; 1.6028x over previous
#include <cuda_runtime.h>
#include <cuda_bf16.h>
#include <cstdint>

// ---------------- scratch (no runtime allocation) ----------------
__device__ __align__(16) unsigned int  g_tgt2[8 * 4096 * 16];        // 2 MiB: 2-bit classes [b][l][ky]
__device__ __align__(16) __nv_bfloat16 g_uconv[32 * 256 * 256];      // 4 MiB: [b*4+c][m][k]
__device__ double g_acc;
__device__ int    g_is32;

// ---------------- helpers ----------------
__device__ __forceinline__ uint32_t smem_u32(const void* p) {
    uint32_t a;
    asm("{ .reg .u64 t; cvta.to.shared.u64 t, %1; cvt.u32.u64 %0, t; }" : "=r"(a) : "l"(p));
    return a;
}

#define ST4(addr, a, b, c, d) \
    asm volatile("st.shared.v4.b32 [%0], {%1,%2,%3,%4};" :: "r"(addr), "r"(a), "r"(b), "r"(c), "r"(d) : "memory")

__device__ __forceinline__ void ldsm_x4(uint32_t& r0, uint32_t& r1, uint32_t& r2, uint32_t& r3, uint32_t addr) {
    asm volatile("ldmatrix.sync.aligned.m8n8.x4.shared.b16 {%0,%1,%2,%3}, [%4];"
                 : "=r"(r0), "=r"(r1), "=r"(r2), "=r"(r3) : "r"(addr));
}
__device__ __forceinline__ void ldsm_x4_t(uint32_t& r0, uint32_t& r1, uint32_t& r2, uint32_t& r3, uint32_t addr) {
    asm volatile("ldmatrix.sync.aligned.m8n8.x4.trans.shared.b16 {%0,%1,%2,%3}, [%4];"
                 : "=r"(r0), "=r"(r1), "=r"(r2), "=r"(r3) : "r"(addr));
}
__device__ __forceinline__ void mma_bf16(float& c0, float& c1, float& c2, float& c3,
                                         uint32_t a0, uint32_t a1, uint32_t a2, uint32_t a3,
                                         uint32_t b0, uint32_t b1) {
    asm volatile("mma.sync.aligned.m16n8k16.row.col.f32.bf16.bf16.f32 "
                 "{%0,%1,%2,%3}, {%4,%5,%6,%7}, {%8,%9}, {%0,%1,%2,%3};"
                 : "+f"(c0), "+f"(c1), "+f"(c2), "+f"(c3)
                 : "r"(a0), "r"(a1), "r"(a2), "r"(a3), "r"(b0), "r"(b1));
}

// ---------------- tiny kernels ----------------
__global__ void zero_kernel() { g_acc = 0.0; g_is32 = 0; }

__global__ void detect_kernel(const unsigned int* __restrict__ t) {
    unsigned int any = 0;
    for (int i = threadIdx.x; i < 8192; i += 256) any |= t[2 * i + 1];
    if (any) g_is32 = 1;   // int32 data: odd words carry real values (nonzero w.h.p.)
}

__global__ void finalize_kernel(float* __restrict__ out) {
    out[0] = (float)(g_acc * (1.0 / 33554432.0));
}

// ---------------- prep: target -> packed 2-bit patch codes + pooled bf16 u_conv ----------------
// grid 128 = 8 b * 16 slabs of 64 rows; 512 threads
__global__ void __launch_bounds__(512) prep_kernel(const void* __restrict__ traw) {
    __shared__ unsigned s_cls[4096];   // [y_local 0..63][x/16], 16 px per word, 2 bits each
    int b = blockIdx.x >> 4, slab = blockIdx.x & 15;

    if (g_is32) {
        const uint4* tb = (const uint4*)((const int*)traw + (((size_t)b) << 20) + (((size_t)slab) << 16));
        for (int w = threadIdx.x; w < 4096; w += 512) {
            int y = w >> 6, xw = w & 63;
            const uint4* p = tb + y * 256 + xw * 4;
            unsigned packed = 0;
#pragma unroll
            for (int i = 0; i < 4; i++) {
                uint4 v = p[i];
                packed |= (v.x & 3u) << (8 * i);
                packed |= (v.y & 3u) << (8 * i + 2);
                packed |= (v.z & 3u) << (8 * i + 4);
                packed |= (v.w & 3u) << (8 * i + 6);
            }
            s_cls[w] = packed;
        }
    } else {
        const longlong2* tb = (const longlong2*)((const long long*)traw + (((size_t)b) << 20) + (((size_t)slab) << 16));
        for (int w = threadIdx.x; w < 4096; w += 512) {
            int y = w >> 6, xw = w & 63;
            const longlong2* p = tb + y * 512 + xw * 8;
            unsigned packed = 0;
#pragma unroll
            for (int i = 0; i < 8; i++) {
                longlong2 v = p[i];
                packed |= ((unsigned)v.x & 3u) << (4 * i);
                packed |= ((unsigned)v.y & 3u) << (4 * i + 2);
            }
            s_cls[w] = packed;
        }
    }
    __syncthreads();

    // --- tgt2: per patch l, 16 words (one per ky), each word = 16 kx classes ---
    unsigned* outb = g_tgt2 + ((size_t)(b * 4096 + slab * 256)) * 16;
    for (int o = threadIdx.x; o < 4096; o += 512) {
        int ky = o >> 8, l_loc = o & 255;
        int Yl = l_loc >> 6, Xl = l_loc & 63;
        outb[l_loc * 16 + ky] = s_cls[(Yl * 16 + ky) * 64 + Xl];
    }

    // --- u_conv: 4x4 pool of one-hot, written transposed as [bc][m][k] bf16 ---
    for (int o = threadIdx.x; o < 4096; o += 512) {
        int yb = o >> 8, xb = o & 255;          // pooled coords (local row, col)
        unsigned w32 = 0;
#pragma unroll
        for (int rr = 0; rr < 4; rr++) {
            unsigned wd = s_cls[(yb * 4 + rr) * 64 + (xb >> 2)];
            w32 |= ((wd >> (8 * (xb & 3))) & 0xFFu) << (8 * rr);   // 16 codes of this 4x4 block
        }
        int y = slab * 16 + yb;                 // global pooled row 0..255
        int m = ((y >> 4) * 16) + (xb >> 4);
        int k = ((y & 15) * 16) + (xb & 15);
#pragma unroll
        for (unsigned c = 0; c < 4; c++) {
            unsigned t = w32 ^ (0x55555555u * c);
            unsigned u = (~t) & ((~t) >> 1) & 0x55555555u;
            float v = (float)__popc(u) * 0.0625f;
            g_uconv[(((size_t)b * 4 + c) * 256 + m) * 256 + k] = __float2bfloat16(v);
        }
    }
}

// ---------------- GEMM (mma.sync bf16) + fused epilogue ----------------
// smem: A 128x256 bf16 (64 KB), B 256x256 bf16 (128 KB); rows 512 B, 16B-chunk XOR swizzle.
#define SM_A      0
#define SM_B      65536
#define SM_TOTAL  (65536 + 131072)

__global__ void __launch_bounds__(256) gemm_kernel(const float* __restrict__ att) {
    extern __shared__ char smem[];
    __shared__ float s_ws[8];
    uint32_t sbase = smem_u32(smem);
    int tid = threadIdx.x, wid = tid >> 5, ln = tid & 31;
    int bc = blockIdx.x >> 5;          // b*4+c
    int lt = blockIdx.x & 31;          // 128-row l tile

    // kick DRAM first: prefetch this CTA's 128 KB attentions tile into L2
    const float* atile = att + ((size_t)bc * 4096 + (size_t)lt * 128) * 256;
    for (int i = tid; i < 1024; i += 256)
        asm volatile("prefetch.global.L2 [%0];" :: "l"(atile + i * 32));

    // ---- A fill: expand 2-bit class codes -> bf16 {0,1} ----
    {
        int b = bc >> 2;
        unsigned c = (unsigned)(bc & 3);
        int l_loc = tid >> 1, half = tid & 1;
        const unsigned* wp = g_tgt2 + ((size_t)(b * 4096 + lt * 128 + l_loc)) * 16 + half * 8;
        uint4 wA = ((const uint4*)wp)[0];
        uint4 wB = ((const uint4*)wp)[1];
        unsigned ws8[8] = {wA.x, wA.y, wA.z, wA.w, wB.x, wB.y, wB.z, wB.w};
        uint32_t rowbase = (uint32_t)(l_loc * 512);
        uint32_t sw = (uint32_t)((l_loc & 7) << 4);
#pragma unroll
        for (int q = 0; q < 8; q++) {
            int ky = half * 8 + q;
            unsigned w = ws8[q];
            uint32_t r[8];
#pragma unroll
            for (int j = 0; j < 8; j++) {
                uint32_t lo = (((w >> (4 * j)) & 3u) == c) ? 0x3F80u : 0u;
                uint32_t hi = (((w >> (4 * j + 2)) & 3u) == c) ? 0x3F800000u : 0u;
                r[j] = lo | hi;
            }
            uint32_t off = (uint32_t)(ky * 32);
            ST4(sbase + SM_A + rowbase + ((off) ^ sw), r[0], r[1], r[2], r[3]);
            ST4(sbase + SM_A + rowbase + ((off + 16) ^ sw), r[4], r[5], r[6], r[7]);
        }
    }

    // ---- B fill: u_conv[bc] (256x256 bf16, K-major) ----
    {
        const uint4* src = (const uint4*)(g_uconv + (size_t)bc * 65536);
        for (int idx = tid; idx < 8192; idx += 256) {
            int m = idx >> 5, u = idx & 31;
            uint4 v = src[m * 32 + u];
            uint32_t addr = (uint32_t)(m * 512) + (((uint32_t)(u * 16)) ^ (uint32_t)((m & 7) << 4));
            ST4(sbase + SM_B + addr, v.x, v.y, v.z, v.w);
        }
    }
    __syncthreads();

    // ---- per-warp tile: 32 l-rows x 128 m-cols, m in 2 chunks of 64 ----
    int l_base = (wid & 3) * 32;
    int m_half = (wid >> 2) * 128;

    int ra0 = l_base + (ln & 15);
    int ra1 = ra0 + 16;
    uint32_t a0base = sbase + SM_A + (uint32_t)(ra0 * 512);
    uint32_t a1base = sbase + SM_A + (uint32_t)(ra1 * 512);
    uint32_t a0sw = (uint32_t)((ra0 & 7) << 4);
    uint32_t a1sw = (uint32_t)((ra1 & 7) << 4);
    uint32_t akb = (uint32_t)((ln >> 4) * 16);
    uint32_t bko = (uint32_t)(((ln >> 3) & 1) * 16);

    float wsum = 0.f;
    const float s256 = 1.f / 256.f;

#pragma unroll
    for (int mc = 0; mc < 2; mc++) {
        int mb = m_half + mc * 64;
        float acc[64];
#pragma unroll
        for (int i = 0; i < 64; i++) acc[i] = 0.f;

        // B x4.trans address bases: lane-group g = ln>>4 selects n-sub pair member,
        // tiles = [nsub 2jj klo, 2jj khi, 2jj+1 klo, 2jj+1 khi]
        uint32_t bbase[4], bsw[4];
#pragma unroll
        for (int jj = 0; jj < 4; jj++) {
            int r = mb + (jj * 2 + (ln >> 4)) * 8 + (ln & 7);
            bbase[jj] = sbase + SM_B + (uint32_t)(r * 512);
            bsw[jj]   = (uint32_t)((r & 7) << 4);
        }

        // ---- software-pipelined k loop (double-buffered fragments) ----
        uint32_t af[2][8], bfr[2][16];

        {   // preload s = 0
            uint32_t ka = akb;
            ldsm_x4(af[0][0], af[0][1], af[0][2], af[0][3], a0base + (ka ^ a0sw));
            ldsm_x4(af[0][4], af[0][5], af[0][6], af[0][7], a1base + (ka ^ a1sw));
            uint32_t kb = bko;
#pragma unroll
            for (int jj = 0; jj < 4; jj++)
                ldsm_x4_t(bfr[0][jj * 4 + 0], bfr[0][jj * 4 + 1], bfr[0][jj * 4 + 2], bfr[0][jj * 4 + 3],
                          bbase[jj] + (kb ^ bsw[jj]));
        }

#pragma unroll
        for (int s = 0; s < 16; s++) {
            int cur = s & 1, nxt = cur ^ 1;
            if (s < 15) {
                uint32_t ka = (uint32_t)((s + 1) * 32) + akb;
                ldsm_x4(af[nxt][0], af[nxt][1], af[nxt][2], af[nxt][3], a0base + (ka ^ a0sw));
                ldsm_x4(af[nxt][4], af[nxt][5], af[nxt][6], af[nxt][7], a1base + (ka ^ a1sw));
                uint32_t kb = (uint32_t)((s + 1) * 32) + bko;
#pragma unroll
                for (int jj = 0; jj < 4; jj++)
                    ldsm_x4_t(bfr[nxt][jj * 4 + 0], bfr[nxt][jj * 4 + 1], bfr[nxt][jj * 4 + 2], bfr[nxt][jj * 4 + 3],
                              bbase[jj] + (kb ^ bsw[jj]));
            }
#pragma unroll
            for (int j = 0; j < 8; j++) {
                uint32_t b0 = bfr[cur][(j >> 1) * 4 + (j & 1) * 2];
                uint32_t b1 = bfr[cur][(j >> 1) * 4 + (j & 1) * 2 + 1];
                mma_bf16(acc[j * 4 + 0], acc[j * 4 + 1], acc[j * 4 + 2], acc[j * 4 + 3],
                         af[cur][0], af[cur][1], af[cur][2], af[cur][3], b0, b1);
                mma_bf16(acc[32 + j * 4 + 0], acc[32 + j * 4 + 1], acc[32 + j * 4 + 2], acc[32 + j * 4 + 3],
                         af[cur][4], af[cur][5], af[cur][6], af[cur][7], b0, b1);
            }
        }

        // ---- fused epilogue for this m-chunk: (att - acc/256)^2 ----
#pragma unroll
        for (int i = 0; i < 2; i++) {
            int R = l_base + i * 16 + (ln >> 2);
#pragma unroll
            for (int j = 0; j < 8; j++) {
                int C = mb + j * 8 + (ln & 3) * 2;
                float2 t0 = __ldg((const float2*)(atile + (size_t)R * 256 + C));
                float2 t1 = __ldg((const float2*)(atile + (size_t)(R + 8) * 256 + C));
                float* a = &acc[i * 32 + j * 4];
                float d0 = t0.x - a[0] * s256;
                float d1 = t0.y - a[1] * s256;
                float d2 = t1.x - a[2] * s256;
                float d3 = t1.y - a[3] * s256;
                wsum += d0 * d0 + d1 * d1 + d2 * d2 + d3 * d3;
            }
        }
    }

    // ---- reduce: warp -> CTA -> one double atomic per CTA ----
#pragma unroll
    for (int off = 16; off; off >>= 1) wsum += __shfl_xor_sync(0xFFFFFFFFu, wsum, off);
    if (ln == 0) s_ws[wid] = wsum;
    __syncthreads();
    if (tid == 0) {
        float t = 0.f;
#pragma unroll
        for (int i = 0; i < 8; i++) t += s_ws[i];
        atomicAdd(&g_acc, (double)t);
    }
}

// ---------------- launch ----------------
extern "C" void kernel_launch(void* const* d_in, const int* in_sizes, int n_in,
                              void* d_out, int out_size) {
    const void*  target = d_in[1];               // int64 or int32 (runtime-detected)
    const float* att    = (const float*)d_in[2]; // (8,4,4096,256)
    (void)in_sizes; (void)n_in; (void)out_size;

    cudaFuncSetAttribute(gemm_kernel, cudaFuncAttributeMaxDynamicSharedMemorySize, SM_TOTAL);

    zero_kernel<<<1, 1>>>();
    detect_kernel<<<1, 256>>>((const unsigned int*)target);
    prep_kernel<<<128, 512>>>(target);
    gemm_kernel<<<1024, 256, SM_TOTAL>>>(att);
    finalize_kernel<<<1, 1>>>((float*)d_out);
}